// round 12
// baseline (speedup 1.0000x reference)
#include <cuda_runtime.h>
#include <cuda_bf16.h>
#include <math.h>
#include <stdint.h>

#define NN 20000
#define EE 180000
#define DD 768
#define SS 512
#define BS 8192      // B*S
#define HH 128       // HEADS*HID
#define STRD 136     // padded SMEM row stride (bf16 elems)

// ---------------- scratch ----------------
__device__ float g_hs1[NN * HH];
__device__ float g_hd1[NN * HH];
__device__ __nv_bfloat16 g_h1h[NN * HH];
__device__ __nv_bfloat16 g_h1l[NN * HH];
__device__ __nv_bfloat16 g_wsh[DD * HH];
__device__ __nv_bfloat16 g_wsl[DD * HH];
__device__ __nv_bfloat16 g_wdh[DD * HH];
__device__ __nv_bfloat16 g_wdl[DD * HH];
__device__ float g_hs2[NN * DD];
__device__ float g_hd2[NN * DD];
__device__ float g_pe [SS * DD];
__device__ int   g_deg[NN];
__device__ int   g_off[NN];     // scan writes start; destructive scatter leaves END
__device__ int   g_flag[NN];
__device__ int   g_list[NN];
__device__ int   g_srcs[EE];
__device__ int   t_head[NN];    // token linked-list heads (-1)
__device__ int   t_next[BS];
__device__ int   g_misc[4];     // [0]=cnt [1..3]=grid barriers
__device__ int   c_bsum[20];

__device__ __forceinline__ float lrelu(float x) { return x > 0.f ? x : 0.2f * x; }
__device__ __forceinline__ float elu1(float x)  { return x > 0.f ? x : expm1f(x); }

__device__ __forceinline__ uint32_t smem_u32(const void* p) {
    uint32_t a;
    asm("{ .reg .u64 t; cvta.to.shared.u64 t, %1; cvt.u32.u64 %0, t; }" : "=r"(a) : "l"(p));
    return a;
}

#define LDSM_X4(r0, r1, r2, r3, addr) \
    asm volatile("ldmatrix.sync.aligned.m8n8.x4.shared.b16 {%0,%1,%2,%3}, [%4];" \
                 : "=r"(r0), "=r"(r1), "=r"(r2), "=r"(r3) : "r"(addr))

#define MMA16816(c, a0, a1, a2, a3, b0, b1) \
    asm volatile("mma.sync.aligned.m16n8k16.row.col.f32.bf16.bf16.f32 " \
                 "{%0,%1,%2,%3}, {%4,%5,%6,%7}, {%8,%9}, {%0,%1,%2,%3};" \
                 : "+f"((c)[0]), "+f"((c)[1]), "+f"((c)[2]), "+f"((c)[3]) \
                 : "r"(a0), "r"(a1), "r"(a2), "r"(a3), "r"(b0), "r"(b1))

// ---------------- grid barrier among first NCSR blocks (all wave-1 resident) ----------------
#define NCSR 296
__device__ __forceinline__ void gbar(int idx) {
    __syncthreads();
    if (threadIdx.x == 0) {
        __threadfence();
        atomicAdd(&g_misc[idx], 1);
        volatile int* c = &g_misc[idx];
        while (*c < NCSR) { __nanosleep(64); }
    }
    __syncthreads();
}

// ---------------- MEGA kernel: CSR (blocks 0..NCSR) + gemm1 + pe + wsplit + tok + tables ----------------
#define MB_G1 (NCSR + 1250)
#define MB_PE (MB_G1 + 1536)
#define MB_WS (MB_PE + 384)
#define MB_TK (MB_WS + 32)
#define MB_TAB (MB_TK + BS)
__global__ void __launch_bounds__(256, 4) k_mega(
        const int* __restrict__ e_src, const int* __restrict__ e_dst,
        const float* __restrict__ feat,
        const float* __restrict__ Ws1, const float* __restrict__ Wd1,
        const float* __restrict__ Ws, const float* __restrict__ Wd,
        const int* __restrict__ trj,
        const int* __restrict__ mins, const int* __restrict__ wkd,
        const int* __restrict__ day, const int* __restrict__ grd,
        const float* __restrict__ grid_tab, const float* __restrict__ dayt_tab,
        const float* __restrict__ wk_tab, const float* __restrict__ day_tab,
        float* __restrict__ out) {
    const int b = blockIdx.x;
    const int tid = threadIdx.x;   // 256

    if (b < NCSR) {
        // ---- phase 1: histogram ----
        for (int e = b * 256 + tid; e < EE; e += NCSR * 256)
            atomicAdd(&g_deg[e_dst[e]], 1);
        gbar(1);

        // ---- phase 2: blocks 0..19 scan 1024-elem chunks ----
        int v4[4], pre[4], texcl = 0, prefix = 0;
        __shared__ int s_w[32];
        if (b < 20) {
            const int base = b * 1024 + tid * 4;
            int local = 0;
#pragma unroll
            for (int i = 0; i < 4; i++) {
                int idx = base + i;
                int v = (idx < NN) ? g_deg[idx] : 0;
                pre[i] = local; local += v; v4[i] = v;
            }
            (void)v4;
            const int lane = tid & 31, wid = tid >> 5;
            int x = local;
#pragma unroll
            for (int o = 1; o < 32; o <<= 1) {
                int y = __shfl_up_sync(0xffffffffu, x, o);
                if (lane >= o) x += y;
            }
            if (lane == 31) s_w[wid] = x;
            __syncthreads();
            if (wid == 0) {
                int s = (lane < 8) ? s_w[lane] : 0;
#pragma unroll
                for (int o = 1; o < 8; o <<= 1) {
                    int y = __shfl_up_sync(0xffffffffu, s, o);
                    if (lane >= o) s += y;
                }
                if (lane < 8) s_w[lane] = s;
            }
            __syncthreads();
            texcl = (x - local) + (wid > 0 ? s_w[wid - 1] : 0);
            if (tid == 0) { c_bsum[b] = s_w[7]; __threadfence(); }
        }
        gbar(2);
        if (b < 20) {
            for (int j = 0; j < b; j++) prefix += c_bsum[j];
            const int base = b * 1024 + tid * 4;
#pragma unroll
            for (int i = 0; i < 4; i++) {
                int idx = base + i;
                if (idx < NN) g_off[idx] = prefix + texcl + pre[i];
            }
        }
        gbar(3);

        // ---- phase 3: destructive scatter ----
        for (int e = b * 256 + tid; e < EE; e += NCSR * 256) {
            int d = e_dst[e];
            int pos = atomicAdd(&g_off[d], 1);
            g_srcs[pos] = e_src[e];
        }
    } else if (b < MB_G1) {
        // ---- layer-1 projections: 16 nodes/block, half threads hs / half hd ----
        __shared__ float w[2][4 * HH];
        int sub = tid >> 7, t = tid & 127;
        const float* W = sub ? Wd1 : Ws1;
        for (int i = t; i < 4 * HH; i += 128) w[sub][i] = W[i];
        __syncthreads();
        float* O = sub ? g_hd1 : g_hs1;
        int n0 = (b - NCSR) * 16, n1 = min(NN, n0 + 16);
        for (int n = n0; n < n1; n++) {
            float4 f = *(const float4*)&feat[n * 4];
            O[n * HH + t] = f.x * w[sub][t] + f.y * w[sub][HH + t]
                          + f.z * w[sub][2 * HH + t] + f.w * w[sub][3 * HH + t];
        }
    } else if (b < MB_PE) {
        int idx = (b - MB_G1) * 256 + tid;
        int s = idx / DD, d = idx % DD;
        int i2 = d >> 1;
        float div = __expf((float)(2 * i2) * (-9.210340371976184f / (float)DD));
        float ang = (float)s * div;
        g_pe[idx] = (d & 1) ? cosf(ang) : sinf(ang);
    } else if (b < MB_WS) {
        int i = (b - MB_PE) * 256 + tid;
        int n = i >> 7, k = i & 127;
        float ws = Ws[k * DD + n];
        __nv_bfloat16 h = __float2bfloat16(ws);
        g_wsh[i] = h;
        g_wsl[i] = __float2bfloat16(ws - __bfloat162float(h));
        float wd = Wd[k * DD + n];
        h = __float2bfloat16(wd);
        g_wdh[i] = h;
        g_wdl[i] = __float2bfloat16(wd - __bfloat162float(h));
    } else if (b < MB_TK) {
        int j = (b - MB_WS) * 256 + tid;
        if (j < BS) {
            int v = trj[j];
            t_next[j] = atomicExch(&t_head[v], j);
            if (atomicExch(&g_flag[v], 1) == 0) {
                int p = atomicAdd(&g_misc[0], 1);
                g_list[p] = v;
            }
        }
    } else {
        // ---- table sums: 1 output row per block, threads 0..191 ----
        int r = b - MB_TK;
        if (tid < 192) {
            int mn = mins[r], wk = wkd[r], dy = day[r], gd = grd[r];
            int s = r & (SS - 1);
            int j = tid * 4;
            float4 a = *(const float4*)&g_pe[s * DD + j];
            float4 c = *(const float4*)&wk_tab[wk * DD + j];
            float4 d = *(const float4*)&dayt_tab[mn * DD + j];
            float4 e = *(const float4*)&day_tab[dy * DD + j];
            float4 f = *(const float4*)&grid_tab[gd * DD + j];
            float4 o;
            o.x = a.x + c.x + d.x + e.x + f.x;
            o.y = a.y + c.y + d.y + e.y + f.y;
            o.z = a.z + c.z + d.z + e.z + f.z;
            o.w = a.w + c.w + d.w + e.w + f.w;
            *(float4*)&out[r * DD + j] = o;
        }
    }
}

// ---------------- layer-1: warp per node, online softmax; emit bf16 hi/lo ----------------
__global__ void k_layer1(const float* __restrict__ attn1) {
    int v = (blockIdx.x << 3) + (threadIdx.x >> 5);
    if (v >= NN) return;
    int lane = threadIdx.x & 31;
    int jb = lane * 4;

    float4 hd = *(const float4*)&g_hd1[v * HH + jb];
    float4 at = *(const float4*)&attn1[jb];
    float4 acc = make_float4(0.f, 0.f, 0.f, 0.f);
    float m = -INFINITY, den = 0.f;

    int dg = g_deg[v];
    int st = g_off[v] - dg;           // END - deg
    for (int e = 0; e < dg; e++) {
        int u = g_srcs[st + e];
        float4 hs = *(const float4*)&g_hs1[u * HH + jb];
        float s = lrelu(hs.x + hd.x) * at.x + lrelu(hs.y + hd.y) * at.y
                + lrelu(hs.z + hd.z) * at.z + lrelu(hs.w + hd.w) * at.w;
        s += __shfl_xor_sync(0xffffffffu, s, 1);
        s += __shfl_xor_sync(0xffffffffu, s, 2);
        float nm = fmaxf(m, s);
        float c = __expf(m - nm);
        float p = __expf(s - nm);
        den = den * c + p;
        acc.x = acc.x * c + p * hs.x;
        acc.y = acc.y * c + p * hs.y;
        acc.z = acc.z * c + p * hs.z;
        acc.w = acc.w * c + p * hs.w;
        m = nm;
    }
    float inv = 1.f / den;
    float o[4];
    o[0] = elu1(acc.x * inv); o[1] = elu1(acc.y * inv);
    o[2] = elu1(acc.z * inv); o[3] = elu1(acc.w * inv);
#pragma unroll
    for (int i = 0; i < 4; i++) {
        __nv_bfloat16 h = __float2bfloat16(o[i]);
        g_h1h[v * HH + jb + i] = h;
        g_h1l[v * HH + jb + i] = __float2bfloat16(o[i] - __bfloat162float(h));
    }
}

// ---------------- layer-2 GEMM: N-resident; A in SMEM once, B streamed 64-col ----------------
__global__ void __launch_bounds__(256, 2) k_gemm2_mma(
        const __nv_bfloat16* __restrict__ Bh0, const __nv_bfloat16* __restrict__ Bl0,
        const __nv_bfloat16* __restrict__ Bh1, const __nv_bfloat16* __restrict__ Bl1,
        float* __restrict__ C0, float* __restrict__ C1) {
    extern __shared__ __nv_bfloat16 sm[];
    __nv_bfloat16* Ah_s = sm;
    __nv_bfloat16* Al_s = sm + 128 * STRD;
    __nv_bfloat16* Bh_s = sm + 2 * 128 * STRD;
    __nv_bfloat16* Bl_s = sm + 2 * 128 * STRD + 64 * STRD;

    const int use_list = blockIdx.y;
    const int M_eff = use_list ? g_misc[0] : NN;
    const int bm = blockIdx.x;
    if (bm * 128 >= M_eff) return;
    const __nv_bfloat16* Bh = use_list ? Bh1 : Bh0;
    const __nv_bfloat16* Bl = use_list ? Bl1 : Bl0;
    float* C = use_list ? C1 : C0;
    const int row0 = bm * 128;
    const int tid = threadIdx.x;

    const uint4 z4 = make_uint4(0, 0, 0, 0);
    for (int i = tid; i < 2048; i += 256) {
        int r = i >> 4, ck = i & 15;
        int so = r * STRD + ck * 8;
        int gr = row0 + r;
        uint4 vh = z4, vl = z4;
        if (gr < M_eff) {
            int rr = use_list ? g_list[gr] : gr;
            vh = *(const uint4*)&g_h1h[rr * HH + ck * 8];
            vl = *(const uint4*)&g_h1l[rr * HH + ck * 8];
        }
        *(uint4*)&Ah_s[so] = vh;
        *(uint4*)&Al_s[so] = vl;
    }

    const int wid = tid >> 5, lane = tid & 31;
    const int wm = (wid >> 1) * 32, wn = (wid & 1) * 32;

    const int a_row = wm + (lane & 15);
    const int a_kof = (lane >> 4) * 8;
    const int q = lane >> 3, rrow = lane & 7;
    const int b_nof = ((q >> 1) ? 8 : 0) + rrow;
    const int b_kof = (q & 1) * 8;

    const uint32_t sAh = smem_u32(Ah_s), sAl = smem_u32(Al_s);
    const uint32_t sBh = smem_u32(Bh_s), sBl = smem_u32(Bl_s);

    const int gid = lane >> 2, tig = lane & 3;
    int grow0 = row0 + wm + gid;
    bool v00 = (grow0      ) < M_eff, v01 = (grow0 + 8 ) < M_eff;
    bool v10 = (grow0 + 16 ) < M_eff, v11 = (grow0 + 24) < M_eff;
    int rr00 = v00 ? (use_list ? g_list[grow0      ] : grow0      ) : 0;
    int rr01 = v01 ? (use_list ? g_list[grow0 + 8  ] : grow0 + 8  ) : 0;
    int rr10 = v10 ? (use_list ? g_list[grow0 + 16 ] : grow0 + 16 ) : 0;
    int rr11 = v11 ? (use_list ? g_list[grow0 + 24 ] : grow0 + 24 ) : 0;

    for (int bn = 0; bn < DD / 64; bn++) {
        const int n0 = bn * 64;
        for (int i = tid; i < 1024; i += 256) {
            int r = i >> 4, ck = i & 15;
            int so = r * STRD + ck * 8;
            int gn = n0 + r;
            *(uint4*)&Bh_s[so] = *(const uint4*)&Bh[gn * HH + ck * 8];
            *(uint4*)&Bl_s[so] = *(const uint4*)&Bl[gn * HH + ck * 8];
        }
        __syncthreads();

        float acc[2][4][4];
#pragma unroll
        for (int mt = 0; mt < 2; mt++)
#pragma unroll
            for (int nt = 0; nt < 4; nt++)
#pragma unroll
                for (int c = 0; c < 4; c++) acc[mt][nt][c] = 0.f;

#pragma unroll
        for (int ks = 0; ks < 8; ks++) {
            const int kbase = ks * 16;
            uint32_t ah[2][4], al[2][4], bh[4][2], bl[4][2];
#pragma unroll
            for (int mt = 0; mt < 2; mt++) {
                uint32_t ad = sAh + ((a_row + mt * 16) * STRD + kbase + a_kof) * 2;
                LDSM_X4(ah[mt][0], ah[mt][1], ah[mt][2], ah[mt][3], ad);
            }
#pragma unroll
            for (int np = 0; np < 2; np++) {
                uint32_t bd = sBh + ((wn + np * 16 + b_nof) * STRD + kbase + b_kof) * 2;
                LDSM_X4(bh[np * 2][0], bh[np * 2][1], bh[np * 2 + 1][0], bh[np * 2 + 1][1], bd);
            }
#pragma unroll
            for (int mt = 0; mt < 2; mt++)
#pragma unroll
                for (int nt = 0; nt < 4; nt++)
                    MMA16816(acc[mt][nt], ah[mt][0], ah[mt][1], ah[mt][2], ah[mt][3],
                             bh[nt][0], bh[nt][1]);
#pragma unroll
            for (int mt = 0; mt < 2; mt++) {
                uint32_t ad = sAl + ((a_row + mt * 16) * STRD + kbase + a_kof) * 2;
                LDSM_X4(al[mt][0], al[mt][1], al[mt][2], al[mt][3], ad);
            }
#pragma unroll
            for (int mt = 0; mt < 2; mt++)
#pragma unroll
                for (int nt = 0; nt < 4; nt++)
                    MMA16816(acc[mt][nt], al[mt][0], al[mt][1], al[mt][2], al[mt][3],
                             bh[nt][0], bh[nt][1]);
#pragma unroll
            for (int np = 0; np < 2; np++) {
                uint32_t bd = sBl + ((wn + np * 16 + b_nof) * STRD + kbase + b_kof) * 2;
                LDSM_X4(bl[np * 2][0], bl[np * 2][1], bl[np * 2 + 1][0], bl[np * 2 + 1][1], bd);
            }
#pragma unroll
            for (int mt = 0; mt < 2; mt++)
#pragma unroll
                for (int nt = 0; nt < 4; nt++)
                    MMA16816(acc[mt][nt], ah[mt][0], ah[mt][1], ah[mt][2], ah[mt][3],
                             bl[nt][0], bl[nt][1]);
        }

#pragma unroll
        for (int mt = 0; mt < 2; mt++) {
            bool v0 = mt ? v10 : v00, v1 = mt ? v11 : v01;
            int r0 = mt ? rr10 : rr00, r1 = mt ? rr11 : rr01;
#pragma unroll
            for (int nt = 0; nt < 4; nt++) {
                int col = n0 + wn + nt * 8 + tig * 2;
                if (v0) *(float2*)&C[(size_t)r0 * DD + col] = make_float2(acc[mt][nt][0], acc[mt][nt][1]);
                if (v1) *(float2*)&C[(size_t)r1 * DD + col] = make_float2(acc[mt][nt][2], acc[mt][nt][3]);
            }
        }
        __syncthreads();
    }
}

// ---------------- layer-2: warp per listed node; adds into out via token list ----------------
__global__ void k_layer2(const float* __restrict__ attn2, float* __restrict__ out) {
    __shared__ float at_sh[DD];
    for (int i = threadIdx.x; i < DD; i += 256) at_sh[i] = attn2[i];
    __syncthreads();

    int li = (blockIdx.x << 3) + (threadIdx.x >> 5);
    if (li >= g_misc[0]) return;
    int v = g_list[li];
    int lane = threadIdx.x & 31;
    int jb = lane * 4;

    float4 hd[6], acc[6];
#pragma unroll
    for (int i = 0; i < 6; i++) {
        hd[i] = *(const float4*)&g_hd2[v * DD + i * 128 + jb];
        acc[i] = make_float4(0.f, 0.f, 0.f, 0.f);
    }
    float m = -INFINITY, den = 0.f;

    int dg = g_deg[v];
    int st = g_off[v] - dg;
    for (int e = 0; e < dg; e++) {
        int u = g_srcs[st + e];
        const float* hrow = &g_hs2[u * DD];
        float4 hs[6];
        float s = 0.f;
#pragma unroll
        for (int i = 0; i < 6; i++) {
            hs[i] = *(const float4*)&hrow[i * 128 + jb];
            float4 a = *(const float4*)&at_sh[i * 128 + jb];
            s += lrelu(hs[i].x + hd[i].x) * a.x + lrelu(hs[i].y + hd[i].y) * a.y
               + lrelu(hs[i].z + hd[i].z) * a.z + lrelu(hs[i].w + hd[i].w) * a.w;
        }
#pragma unroll
        for (int o = 16; o; o >>= 1) s += __shfl_xor_sync(0xffffffffu, s, o);
        float nm = fmaxf(m, s);
        float c = __expf(m - nm);
        float p = __expf(s - nm);
        den = den * c + p;
#pragma unroll
        for (int i = 0; i < 6; i++) {
            acc[i].x = acc[i].x * c + p * hs[i].x;
            acc[i].y = acc[i].y * c + p * hs[i].y;
            acc[i].z = acc[i].z * c + p * hs[i].z;
            acc[i].w = acc[i].w * c + p * hs[i].w;
        }
        m = nm;
    }
    float inv = 1.f / den;
    float4 h2[6];
#pragma unroll
    for (int i = 0; i < 6; i++)
        h2[i] = make_float4(acc[i].x * inv, acc[i].y * inv, acc[i].z * inv, acc[i].w * inv);

    for (int r = t_head[v]; r != -1; r = t_next[r]) {
        float* op = &out[(size_t)r * DD + jb];
#pragma unroll
        for (int i = 0; i < 6; i++) {
            float4 o = *(float4*)&op[i * 128];
            o.x += h2[i].x; o.y += h2[i].y; o.z += h2[i].z; o.w += h2[i].w;
            *(float4*)&op[i * 128] = o;
        }
    }
}

// ---------------- launch ----------------
extern "C" void kernel_launch(void* const* d_in, const int* in_sizes, int n_in,
                              void* d_out, int out_size) {
    const int*   trj      = (const int*)d_in[0];
    const int*   min_list = (const int*)d_in[1];
    const int*   wkd_list = (const int*)d_in[2];
    const int*   day_list = (const int*)d_in[3];
    const int*   grd_list = (const int*)d_in[4];
    const int*   e_src    = (const int*)d_in[6];
    const int*   e_dst    = (const int*)d_in[7];
    const float* feat     = (const float*)d_in[8];
    const float* W_src1   = (const float*)d_in[9];
    const float* W_dst1   = (const float*)d_in[10];
    const float* attn1    = (const float*)d_in[11];
    const float* W_src2   = (const float*)d_in[12];
    const float* W_dst2   = (const float*)d_in[13];
    const float* attn2    = (const float*)d_in[14];
    const float* grid_tab = (const float*)d_in[15];
    const float* dayt_tab = (const float*)d_in[16];
    const float* wk_tab   = (const float*)d_in[17];
    const float* day_tab  = (const float*)d_in[18];
    float* out = (float*)d_out;

    const int smem_bytes = (2 * 128 + 2 * 64) * STRD * 2;   // 104448
    static bool once = false;
    static void *p_deg, *p_flag, *p_thead, *p_misc;
    if (!once) {
        cudaFuncSetAttribute(k_gemm2_mma, cudaFuncAttributeMaxDynamicSharedMemorySize, smem_bytes);
        cudaGetSymbolAddress(&p_deg, g_deg);
        cudaGetSymbolAddress(&p_flag, g_flag);
        cudaGetSymbolAddress(&p_thead, t_head);
        cudaGetSymbolAddress(&p_misc, g_misc);
        once = true;
    }

    __nv_bfloat16 *wsh, *wsl, *wdh, *wdl;
    cudaGetSymbolAddress((void**)&wsh, g_wsh);
    cudaGetSymbolAddress((void**)&wsl, g_wsl);
    cudaGetSymbolAddress((void**)&wdh, g_wdh);
    cudaGetSymbolAddress((void**)&wdl, g_wdl);
    float *hs2, *hd2;
    cudaGetSymbolAddress((void**)&hs2, g_hs2);
    cudaGetSymbolAddress((void**)&hd2, g_hd2);

    cudaMemsetAsync(p_deg, 0, NN * sizeof(int), 0);
    cudaMemsetAsync(p_flag, 0, NN * sizeof(int), 0);
    cudaMemsetAsync(p_thead, 0xFF, NN * sizeof(int), 0);    // -1
    cudaMemsetAsync(p_misc, 0, 4 * sizeof(int), 0);

    k_mega<<<MB_TAB, 256>>>(e_src, e_dst, feat, W_src1, W_dst1, W_src2, W_dst2,
                            trj, min_list, wkd_list, day_list, grd_list,
                            grid_tab, dayt_tab, wk_tab, day_tab, out);   // 1
    k_layer1<<<(NN + 7) / 8, 256>>>(attn1);                               // 2
    dim3 g2((NN + 127) / 128, 2);
    k_gemm2_mma<<<g2, 256, smem_bytes>>>(wsh, wsl, wdh, wdl, hs2, hd2);   // 3
    k_layer2<<<(NN + 7) / 8, 256>>>(attn2, out);                          // 4 <- profiled
}

// round 13
// speedup vs baseline: 1.0297x; 1.0297x over previous
#include <cuda_runtime.h>
#include <cuda_bf16.h>
#include <math.h>
#include <stdint.h>

#define NN 20000
#define EE 180000
#define DD 768
#define SS 512
#define BS 8192      // B*S
#define HH 128       // HEADS*HID
#define STRD 136     // padded SMEM row stride (bf16 elems)

// ---------------- scratch ----------------
__device__ float g_hs1[NN * HH];
__device__ float g_hd1[NN * HH];
__device__ __nv_bfloat16 g_h1h[NN * HH];
__device__ __nv_bfloat16 g_h1l[NN * HH];
__device__ __nv_bfloat16 g_wsh[DD * HH];
__device__ __nv_bfloat16 g_wsl[DD * HH];
__device__ __nv_bfloat16 g_wdh[DD * HH];
__device__ __nv_bfloat16 g_wdl[DD * HH];
__device__ float g_hs2[NN * DD];
__device__ float g_hd2[NN * DD];
__device__ float g_pe [SS * DD];
__device__ int   g_deg[NN];
__device__ int   g_off[NN];     // scan writes start; destructive scatter leaves END
__device__ int   g_flag[NN];
__device__ int   g_list[NN];
__device__ int   g_srcs[EE];
__device__ int   t_head[NN];    // token linked-list heads (-1)
__device__ int   t_next[BS];
__device__ int   g_misc[4];     // [0]=cnt [1..3]=grid barriers
__device__ int   c_bsum[20];

__device__ __forceinline__ float lrelu(float x) { return x > 0.f ? x : 0.2f * x; }
__device__ __forceinline__ float elu1(float x)  { return x > 0.f ? x : expm1f(x); }

__device__ __forceinline__ uint32_t smem_u32(const void* p) {
    uint32_t a;
    asm("{ .reg .u64 t; cvta.to.shared.u64 t, %1; cvt.u32.u64 %0, t; }" : "=r"(a) : "l"(p));
    return a;
}

#define LDSM_X4(r0, r1, r2, r3, addr) \
    asm volatile("ldmatrix.sync.aligned.m8n8.x4.shared.b16 {%0,%1,%2,%3}, [%4];" \
                 : "=r"(r0), "=r"(r1), "=r"(r2), "=r"(r3) : "r"(addr))

#define MMA16816(c, a0, a1, a2, a3, b0, b1) \
    asm volatile("mma.sync.aligned.m16n8k16.row.col.f32.bf16.bf16.f32 " \
                 "{%0,%1,%2,%3}, {%4,%5,%6,%7}, {%8,%9}, {%0,%1,%2,%3};" \
                 : "+f"((c)[0]), "+f"((c)[1]), "+f"((c)[2]), "+f"((c)[3]) \
                 : "r"(a0), "r"(a1), "r"(a2), "r"(a3), "r"(b0), "r"(b1))

// ---------------- trivial init kernel (also shifts ncu to profile gemm2 as launch #4) ----------------
__global__ void k_zero() {
    if (threadIdx.x < 4) g_misc[threadIdx.x] = 0;
}

// ---------------- grid barrier among first NCSR blocks (all wave-1 resident) ----------------
#define NCSR 296
__device__ __forceinline__ void gbar(int idx) {
    __syncthreads();
    if (threadIdx.x == 0) {
        __threadfence();
        atomicAdd(&g_misc[idx], 1);
        volatile int* c = &g_misc[idx];
        while (*c < NCSR) { __nanosleep(64); }
    }
    __syncthreads();
}

// ---------------- MEGA kernel: CSR (blocks 0..NCSR) + gemm1 + pe + wsplit + tok + tables ----------------
#define MB_G1 (NCSR + 1250)
#define MB_PE (MB_G1 + 1536)
#define MB_WS (MB_PE + 384)
#define MB_TK (MB_WS + 32)
#define MB_TAB (MB_TK + BS)
__global__ void __launch_bounds__(256, 4) k_mega(
        const int* __restrict__ e_src, const int* __restrict__ e_dst,
        const float* __restrict__ feat,
        const float* __restrict__ Ws1, const float* __restrict__ Wd1,
        const float* __restrict__ Ws, const float* __restrict__ Wd,
        const int* __restrict__ trj,
        const int* __restrict__ mins, const int* __restrict__ wkd,
        const int* __restrict__ day, const int* __restrict__ grd,
        const float* __restrict__ grid_tab, const float* __restrict__ dayt_tab,
        const float* __restrict__ wk_tab, const float* __restrict__ day_tab,
        float* __restrict__ out) {
    const int b = blockIdx.x;
    const int tid = threadIdx.x;   // 256

    if (b < NCSR) {
        // ---- phase 1: histogram ----
        for (int e = b * 256 + tid; e < EE; e += NCSR * 256)
            atomicAdd(&g_deg[e_dst[e]], 1);
        gbar(1);

        // ---- phase 2: blocks 0..19 scan 1024-elem chunks ----
        int pre[4], texcl = 0, prefix = 0;
        __shared__ int s_w[32];
        if (b < 20) {
            const int base = b * 1024 + tid * 4;
            int local = 0;
#pragma unroll
            for (int i = 0; i < 4; i++) {
                int idx = base + i;
                int v = (idx < NN) ? g_deg[idx] : 0;
                pre[i] = local; local += v;
            }
            const int lane = tid & 31, wid = tid >> 5;
            int x = local;
#pragma unroll
            for (int o = 1; o < 32; o <<= 1) {
                int y = __shfl_up_sync(0xffffffffu, x, o);
                if (lane >= o) x += y;
            }
            if (lane == 31) s_w[wid] = x;
            __syncthreads();
            if (wid == 0) {
                int s = (lane < 8) ? s_w[lane] : 0;
#pragma unroll
                for (int o = 1; o < 8; o <<= 1) {
                    int y = __shfl_up_sync(0xffffffffu, s, o);
                    if (lane >= o) s += y;
                }
                if (lane < 8) s_w[lane] = s;
            }
            __syncthreads();
            texcl = (x - local) + (wid > 0 ? s_w[wid - 1] : 0);
            if (tid == 0) { c_bsum[b] = s_w[7]; __threadfence(); }
        }
        gbar(2);
        if (b < 20) {
            for (int j = 0; j < b; j++) prefix += c_bsum[j];
            const int base = b * 1024 + tid * 4;
#pragma unroll
            for (int i = 0; i < 4; i++) {
                int idx = base + i;
                if (idx < NN) g_off[idx] = prefix + texcl + pre[i];
            }
        }
        gbar(3);

        // ---- phase 3: destructive scatter ----
        for (int e = b * 256 + tid; e < EE; e += NCSR * 256) {
            int d = e_dst[e];
            int pos = atomicAdd(&g_off[d], 1);
            g_srcs[pos] = e_src[e];
        }
    } else if (b < MB_G1) {
        // ---- layer-1 projections: 16 nodes/block, half threads hs / half hd ----
        __shared__ float w[2][4 * HH];
        int sub = tid >> 7, t = tid & 127;
        const float* W = sub ? Wd1 : Ws1;
        for (int i = t; i < 4 * HH; i += 128) w[sub][i] = W[i];
        __syncthreads();
        float* O = sub ? g_hd1 : g_hs1;
        int n0 = (b - NCSR) * 16, n1 = min(NN, n0 + 16);
        for (int n = n0; n < n1; n++) {
            float4 f = *(const float4*)&feat[n * 4];
            O[n * HH + t] = f.x * w[sub][t] + f.y * w[sub][HH + t]
                          + f.z * w[sub][2 * HH + t] + f.w * w[sub][3 * HH + t];
        }
    } else if (b < MB_PE) {
        int idx = (b - MB_G1) * 256 + tid;
        int s = idx / DD, d = idx % DD;
        int i2 = d >> 1;
        float div = __expf((float)(2 * i2) * (-9.210340371976184f / (float)DD));
        float ang = (float)s * div;
        g_pe[idx] = (d & 1) ? cosf(ang) : sinf(ang);
    } else if (b < MB_WS) {
        int i = (b - MB_PE) * 256 + tid;
        int n = i >> 7, k = i & 127;
        float ws = Ws[k * DD + n];
        __nv_bfloat16 h = __float2bfloat16(ws);
        g_wsh[i] = h;
        g_wsl[i] = __float2bfloat16(ws - __bfloat162float(h));
        float wd = Wd[k * DD + n];
        h = __float2bfloat16(wd);
        g_wdh[i] = h;
        g_wdl[i] = __float2bfloat16(wd - __bfloat162float(h));
    } else if (b < MB_TK) {
        int j = (b - MB_WS) * 256 + tid;
        if (j < BS) {
            int v = trj[j];
            t_next[j] = atomicExch(&t_head[v], j);
            if (atomicExch(&g_flag[v], 1) == 0) {
                int p = atomicAdd(&g_misc[0], 1);
                g_list[p] = v;
            }
        }
    } else {
        // ---- table sums: 1 output row per block, threads 0..191 ----
        int r = b - MB_TK;
        if (tid < 192) {
            int mn = mins[r], wk = wkd[r], dy = day[r], gd = grd[r];
            int s = r & (SS - 1);
            int j = tid * 4;
            float4 a = *(const float4*)&g_pe[s * DD + j];
            float4 c = *(const float4*)&wk_tab[wk * DD + j];
            float4 d = *(const float4*)&dayt_tab[mn * DD + j];
            float4 e = *(const float4*)&day_tab[dy * DD + j];
            float4 f = *(const float4*)&grid_tab[gd * DD + j];
            float4 o;
            o.x = a.x + c.x + d.x + e.x + f.x;
            o.y = a.y + c.y + d.y + e.y + f.y;
            o.z = a.z + c.z + d.z + e.z + f.z;
            o.w = a.w + c.w + d.w + e.w + f.w;
            *(float4*)&out[r * DD + j] = o;
        }
    }
}

// ---------------- layer-1: warp per node, online softmax; emit bf16 hi/lo ----------------
__global__ void k_layer1(const float* __restrict__ attn1) {
    int v = (blockIdx.x << 3) + (threadIdx.x >> 5);
    if (v >= NN) return;
    int lane = threadIdx.x & 31;
    int jb = lane * 4;

    float4 hd = *(const float4*)&g_hd1[v * HH + jb];
    float4 at = *(const float4*)&attn1[jb];
    float4 acc = make_float4(0.f, 0.f, 0.f, 0.f);
    float m = -INFINITY, den = 0.f;

    int dg = g_deg[v];
    int st = g_off[v] - dg;           // END - deg
    for (int e = 0; e < dg; e++) {
        int u = g_srcs[st + e];
        float4 hs = *(const float4*)&g_hs1[u * HH + jb];
        float s = lrelu(hs.x + hd.x) * at.x + lrelu(hs.y + hd.y) * at.y
                + lrelu(hs.z + hd.z) * at.z + lrelu(hs.w + hd.w) * at.w;
        s += __shfl_xor_sync(0xffffffffu, s, 1);
        s += __shfl_xor_sync(0xffffffffu, s, 2);
        float nm = fmaxf(m, s);
        float c = __expf(m - nm);
        float p = __expf(s - nm);
        den = den * c + p;
        acc.x = acc.x * c + p * hs.x;
        acc.y = acc.y * c + p * hs.y;
        acc.z = acc.z * c + p * hs.z;
        acc.w = acc.w * c + p * hs.w;
        m = nm;
    }
    float inv = 1.f / den;
    float o[4];
    o[0] = elu1(acc.x * inv); o[1] = elu1(acc.y * inv);
    o[2] = elu1(acc.z * inv); o[3] = elu1(acc.w * inv);
#pragma unroll
    for (int i = 0; i < 4; i++) {
        __nv_bfloat16 h = __float2bfloat16(o[i]);
        g_h1h[v * HH + jb + i] = h;
        g_h1l[v * HH + jb + i] = __float2bfloat16(o[i] - __bfloat162float(h));
    }
}

// ---------------- layer-2 GEMM: N-resident; A in SMEM once, B streamed 64-col ----------------
__global__ void __launch_bounds__(256, 2) k_gemm2_mma(
        const __nv_bfloat16* __restrict__ Bh0, const __nv_bfloat16* __restrict__ Bl0,
        const __nv_bfloat16* __restrict__ Bh1, const __nv_bfloat16* __restrict__ Bl1,
        float* __restrict__ C0, float* __restrict__ C1) {
    extern __shared__ __nv_bfloat16 sm[];
    __nv_bfloat16* Ah_s = sm;
    __nv_bfloat16* Al_s = sm + 128 * STRD;
    __nv_bfloat16* Bh_s = sm + 2 * 128 * STRD;
    __nv_bfloat16* Bl_s = sm + 2 * 128 * STRD + 64 * STRD;

    const int use_list = blockIdx.y;
    const int M_eff = use_list ? g_misc[0] : NN;
    const int bm = blockIdx.x;
    if (bm * 128 >= M_eff) return;
    const __nv_bfloat16* Bh = use_list ? Bh1 : Bh0;
    const __nv_bfloat16* Bl = use_list ? Bl1 : Bl0;
    float* C = use_list ? C1 : C0;
    const int row0 = bm * 128;
    const int tid = threadIdx.x;

    const uint4 z4 = make_uint4(0, 0, 0, 0);
    for (int i = tid; i < 2048; i += 256) {
        int r = i >> 4, ck = i & 15;
        int so = r * STRD + ck * 8;
        int gr = row0 + r;
        uint4 vh = z4, vl = z4;
        if (gr < M_eff) {
            int rr = use_list ? g_list[gr] : gr;
            vh = *(const uint4*)&g_h1h[rr * HH + ck * 8];
            vl = *(const uint4*)&g_h1l[rr * HH + ck * 8];
        }
        *(uint4*)&Ah_s[so] = vh;
        *(uint4*)&Al_s[so] = vl;
    }

    const int wid = tid >> 5, lane = tid & 31;
    const int wm = (wid >> 1) * 32, wn = (wid & 1) * 32;

    const int a_row = wm + (lane & 15);
    const int a_kof = (lane >> 4) * 8;
    const int q = lane >> 3, rrow = lane & 7;
    const int b_nof = ((q >> 1) ? 8 : 0) + rrow;
    const int b_kof = (q & 1) * 8;

    const uint32_t sAh = smem_u32(Ah_s), sAl = smem_u32(Al_s);
    const uint32_t sBh = smem_u32(Bh_s), sBl = smem_u32(Bl_s);

    const int gid = lane >> 2, tig = lane & 3;
    int grow0 = row0 + wm + gid;
    bool v00 = (grow0      ) < M_eff, v01 = (grow0 + 8 ) < M_eff;
    bool v10 = (grow0 + 16 ) < M_eff, v11 = (grow0 + 24) < M_eff;
    int rr00 = v00 ? (use_list ? g_list[grow0      ] : grow0      ) : 0;
    int rr01 = v01 ? (use_list ? g_list[grow0 + 8  ] : grow0 + 8  ) : 0;
    int rr10 = v10 ? (use_list ? g_list[grow0 + 16 ] : grow0 + 16 ) : 0;
    int rr11 = v11 ? (use_list ? g_list[grow0 + 24 ] : grow0 + 24 ) : 0;

    for (int bn = 0; bn < DD / 64; bn++) {
        const int n0 = bn * 64;
        for (int i = tid; i < 1024; i += 256) {
            int r = i >> 4, ck = i & 15;
            int so = r * STRD + ck * 8;
            int gn = n0 + r;
            *(uint4*)&Bh_s[so] = *(const uint4*)&Bh[gn * HH + ck * 8];
            *(uint4*)&Bl_s[so] = *(const uint4*)&Bl[gn * HH + ck * 8];
        }
        __syncthreads();

        float acc[2][4][4];
#pragma unroll
        for (int mt = 0; mt < 2; mt++)
#pragma unroll
            for (int nt = 0; nt < 4; nt++)
#pragma unroll
                for (int c = 0; c < 4; c++) acc[mt][nt][c] = 0.f;

#pragma unroll
        for (int ks = 0; ks < 8; ks++) {
            const int kbase = ks * 16;
            uint32_t ah[2][4], al[2][4], bh[4][2], bl[4][2];
#pragma unroll
            for (int mt = 0; mt < 2; mt++) {
                uint32_t ad = sAh + ((a_row + mt * 16) * STRD + kbase + a_kof) * 2;
                LDSM_X4(ah[mt][0], ah[mt][1], ah[mt][2], ah[mt][3], ad);
            }
#pragma unroll
            for (int np = 0; np < 2; np++) {
                uint32_t bd = sBh + ((wn + np * 16 + b_nof) * STRD + kbase + b_kof) * 2;
                LDSM_X4(bh[np * 2][0], bh[np * 2][1], bh[np * 2 + 1][0], bh[np * 2 + 1][1], bd);
            }
#pragma unroll
            for (int mt = 0; mt < 2; mt++)
#pragma unroll
                for (int nt = 0; nt < 4; nt++)
                    MMA16816(acc[mt][nt], ah[mt][0], ah[mt][1], ah[mt][2], ah[mt][3],
                             bh[nt][0], bh[nt][1]);
#pragma unroll
            for (int mt = 0; mt < 2; mt++) {
                uint32_t ad = sAl + ((a_row + mt * 16) * STRD + kbase + a_kof) * 2;
                LDSM_X4(al[mt][0], al[mt][1], al[mt][2], al[mt][3], ad);
            }
#pragma unroll
            for (int mt = 0; mt < 2; mt++)
#pragma unroll
                for (int nt = 0; nt < 4; nt++)
                    MMA16816(acc[mt][nt], al[mt][0], al[mt][1], al[mt][2], al[mt][3],
                             bh[nt][0], bh[nt][1]);
#pragma unroll
            for (int np = 0; np < 2; np++) {
                uint32_t bd = sBl + ((wn + np * 16 + b_nof) * STRD + kbase + b_kof) * 2;
                LDSM_X4(bl[np * 2][0], bl[np * 2][1], bl[np * 2 + 1][0], bl[np * 2 + 1][1], bd);
            }
#pragma unroll
            for (int mt = 0; mt < 2; mt++)
#pragma unroll
                for (int nt = 0; nt < 4; nt++)
                    MMA16816(acc[mt][nt], ah[mt][0], ah[mt][1], ah[mt][2], ah[mt][3],
                             bl[nt][0], bl[nt][1]);
        }

#pragma unroll
        for (int mt = 0; mt < 2; mt++) {
            bool v0 = mt ? v10 : v00, v1 = mt ? v11 : v01;
            int r0 = mt ? rr10 : rr00, r1 = mt ? rr11 : rr01;
#pragma unroll
            for (int nt = 0; nt < 4; nt++) {
                int col = n0 + wn + nt * 8 + tig * 2;
                if (v0) *(float2*)&C[(size_t)r0 * DD + col] = make_float2(acc[mt][nt][0], acc[mt][nt][1]);
                if (v1) *(float2*)&C[(size_t)r1 * DD + col] = make_float2(acc[mt][nt][2], acc[mt][nt][3]);
            }
        }
        __syncthreads();
    }
}

// ---------------- layer-2: TWO warps per node (384 dims each); adds into out via token list ----------------
__global__ void __launch_bounds__(256) k_layer2(const float* __restrict__ attn2,
                                                float* __restrict__ out) {
    __shared__ float at_sh[DD];
    __shared__ float s_part[4][4];      // [pair][w2 + 2*(e&1)] double-buffered partial scores
    for (int i = threadIdx.x; i < DD; i += 256) at_sh[i] = attn2[i];
    __syncthreads();

    const int pair = threadIdx.x >> 6;            // 0..3 (node slot in block)
    const int li = blockIdx.x * 4 + pair;
    if (li >= g_misc[0]) return;                  // whole 64-thread pair exits together
    const int v = g_list[li];
    const int t64 = threadIdx.x & 63;
    const int w2 = t64 >> 5;                      // which half of dims
    const int lane = t64 & 31;
    const int dbase = w2 * 384 + lane * 4;        // + i*128, i=0..2
    const int barid = 8 + pair;

    float4 hd[3], acc[3], at[3];
#pragma unroll
    for (int i = 0; i < 3; i++) {
        hd[i] = *(const float4*)&g_hd2[v * DD + dbase + i * 128];
        at[i] = *(const float4*)&at_sh[dbase + i * 128];
        acc[i] = make_float4(0.f, 0.f, 0.f, 0.f);
    }
    float m = -INFINITY, den = 0.f;

    const int dg = g_deg[v];
    const int st = g_off[v] - dg;
    for (int e = 0; e < dg; e++) {
        int u = g_srcs[st + e];
        const float* hrow = &g_hs2[u * DD];
        float4 hs[3];
        float s = 0.f;
#pragma unroll
        for (int i = 0; i < 3; i++) {
            hs[i] = *(const float4*)&hrow[dbase + i * 128];
            s += lrelu(hs[i].x + hd[i].x) * at[i].x + lrelu(hs[i].y + hd[i].y) * at[i].y
               + lrelu(hs[i].z + hd[i].z) * at[i].z + lrelu(hs[i].w + hd[i].w) * at[i].w;
        }
#pragma unroll
        for (int o = 16; o; o >>= 1) s += __shfl_xor_sync(0xffffffffu, s, o);
        int buf = (e & 1) * 2;
        if (lane == 0) s_part[pair][w2 + buf] = s;
        asm volatile("bar.sync %0, %1;" :: "r"(barid), "r"(64) : "memory");
        float stot = s_part[pair][buf] + s_part[pair][buf + 1];

        float nm = fmaxf(m, stot);
        float c = __expf(m - nm);
        float p = __expf(stot - nm);
        den = den * c + p;
#pragma unroll
        for (int i = 0; i < 3; i++) {
            acc[i].x = acc[i].x * c + p * hs[i].x;
            acc[i].y = acc[i].y * c + p * hs[i].y;
            acc[i].z = acc[i].z * c + p * hs[i].z;
            acc[i].w = acc[i].w * c + p * hs[i].w;
        }
        m = nm;
    }
    float inv = 1.f / den;
    float4 h2[3];
#pragma unroll
    for (int i = 0; i < 3; i++)
        h2[i] = make_float4(acc[i].x * inv, acc[i].y * inv, acc[i].z * inv, acc[i].w * inv);

    // walk this node's token list; each warp writes its 384-dim half
    for (int r = t_head[v]; r != -1; r = t_next[r]) {
        float* op = &out[(size_t)r * DD + dbase];
#pragma unroll
        for (int i = 0; i < 3; i++) {
            float4 o = *(float4*)&op[i * 128];
            o.x += h2[i].x; o.y += h2[i].y; o.z += h2[i].z; o.w += h2[i].w;
            *(float4*)&op[i * 128] = o;
        }
    }
}

// ---------------- launch ----------------
extern "C" void kernel_launch(void* const* d_in, const int* in_sizes, int n_in,
                              void* d_out, int out_size) {
    const int*   trj      = (const int*)d_in[0];
    const int*   min_list = (const int*)d_in[1];
    const int*   wkd_list = (const int*)d_in[2];
    const int*   day_list = (const int*)d_in[3];
    const int*   grd_list = (const int*)d_in[4];
    const int*   e_src    = (const int*)d_in[6];
    const int*   e_dst    = (const int*)d_in[7];
    const float* feat     = (const float*)d_in[8];
    const float* W_src1   = (const float*)d_in[9];
    const float* W_dst1   = (const float*)d_in[10];
    const float* attn1    = (const float*)d_in[11];
    const float* W_src2   = (const float*)d_in[12];
    const float* W_dst2   = (const float*)d_in[13];
    const float* attn2    = (const float*)d_in[14];
    const float* grid_tab = (const float*)d_in[15];
    const float* dayt_tab = (const float*)d_in[16];
    const float* wk_tab   = (const float*)d_in[17];
    const float* day_tab  = (const float*)d_in[18];
    float* out = (float*)d_out;

    const int smem_bytes = (2 * 128 + 2 * 64) * STRD * 2;   // 104448
    static bool once = false;
    static void *p_deg, *p_flag, *p_thead;
    if (!once) {
        cudaFuncSetAttribute(k_gemm2_mma, cudaFuncAttributeMaxDynamicSharedMemorySize, smem_bytes);
        cudaGetSymbolAddress(&p_deg, g_deg);
        cudaGetSymbolAddress(&p_flag, g_flag);
        cudaGetSymbolAddress(&p_thead, t_head);
        once = true;
    }

    __nv_bfloat16 *wsh, *wsl, *wdh, *wdl;
    cudaGetSymbolAddress((void**)&wsh, g_wsh);
    cudaGetSymbolAddress((void**)&wsl, g_wsl);
    cudaGetSymbolAddress((void**)&wdh, g_wdh);
    cudaGetSymbolAddress((void**)&wdl, g_wdl);
    float *hs2, *hd2;
    cudaGetSymbolAddress((void**)&hs2, g_hs2);
    cudaGetSymbolAddress((void**)&hd2, g_hd2);

    cudaMemsetAsync(p_deg, 0, NN * sizeof(int), 0);
    cudaMemsetAsync(p_flag, 0, NN * sizeof(int), 0);
    cudaMemsetAsync(p_thead, 0xFF, NN * sizeof(int), 0);    // -1

    k_zero<<<1, 32>>>();                                                  // 1
    k_mega<<<MB_TAB, 256>>>(e_src, e_dst, feat, W_src1, W_dst1, W_src2, W_dst2,
                            trj, min_list, wkd_list, day_list, grd_list,
                            grid_tab, dayt_tab, wk_tab, day_tab, out);    // 2
    k_layer1<<<(NN + 7) / 8, 256>>>(attn1);                               // 3
    dim3 g2((NN + 127) / 128, 2);
    k_gemm2_mma<<<g2, 256, smem_bytes>>>(wsh, wsl, wdh, wdl, hs2, hd2);   // 4 <- profiled
    k_layer2<<<(NN + 3) / 4, 256>>>(attn2, out);                          // 5
}

// round 14
// speedup vs baseline: 1.0459x; 1.0158x over previous
#include <cuda_runtime.h>
#include <cuda_bf16.h>
#include <math.h>
#include <stdint.h>

#define NN 20000
#define EE 180000
#define DD 768
#define SS 512
#define BS 8192      // B*S
#define HH 128       // HEADS*HID
#define STRD 136     // padded SMEM row stride (bf16 elems)

// ---------------- scratch ----------------
__device__ float g_hs1[NN * HH];
__device__ float g_hd1[NN * HH];
__device__ __nv_bfloat16 g_h1h[NN * HH];
__device__ __nv_bfloat16 g_h1l[NN * HH];
__device__ __nv_bfloat16 g_wsh[DD * HH];
__device__ __nv_bfloat16 g_wsl[DD * HH];
__device__ __nv_bfloat16 g_wdh[DD * HH];
__device__ __nv_bfloat16 g_wdl[DD * HH];
__device__ float g_hs2[NN * DD];
__device__ float g_hd2[NN * DD];
__device__ float g_pe [SS * DD];
__device__ int   g_deg[NN];
__device__ int   g_off[NN];     // scan writes start; destructive scatter leaves END
__device__ int   g_flag[NN];
__device__ int   g_list[NN];
__device__ int   g_srcs[EE];
__device__ int   t_head[NN];    // token linked-list heads (-1)
__device__ int   t_next[BS];
__device__ int   g_misc[4];     // [0]=cnt [1..3]=grid barriers
__device__ int   c_bsum[20];

__device__ __forceinline__ float lrelu(float x) { return x > 0.f ? x : 0.2f * x; }
__device__ __forceinline__ float elu1(float x)  { return x > 0.f ? x : expm1f(x); }

__device__ __forceinline__ uint32_t smem_u32(const void* p) {
    uint32_t a;
    asm("{ .reg .u64 t; cvta.to.shared.u64 t, %1; cvt.u32.u64 %0, t; }" : "=r"(a) : "l"(p));
    return a;
}

#define LDSM_X4(r0, r1, r2, r3, addr) \
    asm volatile("ldmatrix.sync.aligned.m8n8.x4.shared.b16 {%0,%1,%2,%3}, [%4];" \
                 : "=r"(r0), "=r"(r1), "=r"(r2), "=r"(r3) : "r"(addr))

#define MMA16816(c, a0, a1, a2, a3, b0, b1) \
    asm volatile("mma.sync.aligned.m16n8k16.row.col.f32.bf16.bf16.f32 " \
                 "{%0,%1,%2,%3}, {%4,%5,%6,%7}, {%8,%9}, {%0,%1,%2,%3};" \
                 : "+f"((c)[0]), "+f"((c)[1]), "+f"((c)[2]), "+f"((c)[3]) \
                 : "r"(a0), "r"(a1), "r"(a2), "r"(a3), "r"(b0), "r"(b1))

#define CP_ASYNC16(smaddr, gptr) \
    asm volatile("cp.async.cg.shared.global [%0], [%1], 16;" :: "r"(smaddr), "l"(gptr))
#define CP_COMMIT() asm volatile("cp.async.commit_group;" ::: "memory")
#define CP_WAIT1()  asm volatile("cp.async.wait_group 1;" ::: "memory")
#define CP_WAIT0()  asm volatile("cp.async.wait_group 0;" ::: "memory")

// ---------------- trivial init kernel ----------------
__global__ void k_zero() {
    if (threadIdx.x < 4) g_misc[threadIdx.x] = 0;
}

// ---------------- grid barrier among first NCSR blocks (all wave-1 resident) ----------------
#define NCSR 296
__device__ __forceinline__ void gbar(int idx) {
    __syncthreads();
    if (threadIdx.x == 0) {
        __threadfence();
        atomicAdd(&g_misc[idx], 1);
        volatile int* c = &g_misc[idx];
        while (*c < NCSR) { __nanosleep(64); }
    }
    __syncthreads();
}

// ---------------- MEGA kernel: CSR (blocks 0..NCSR) + gemm1 + pe + wsplit + tok + tables ----------------
#define MB_G1 (NCSR + 1250)
#define MB_PE (MB_G1 + 1536)
#define MB_WS (MB_PE + 384)
#define MB_TK (MB_WS + 32)
#define MB_TAB (MB_TK + BS)
__global__ void __launch_bounds__(256, 4) k_mega(
        const int* __restrict__ e_src, const int* __restrict__ e_dst,
        const float* __restrict__ feat,
        const float* __restrict__ Ws1, const float* __restrict__ Wd1,
        const float* __restrict__ Ws, const float* __restrict__ Wd,
        const int* __restrict__ trj,
        const int* __restrict__ mins, const int* __restrict__ wkd,
        const int* __restrict__ day, const int* __restrict__ grd,
        const float* __restrict__ grid_tab, const float* __restrict__ dayt_tab,
        const float* __restrict__ wk_tab, const float* __restrict__ day_tab,
        float* __restrict__ out) {
    const int b = blockIdx.x;
    const int tid = threadIdx.x;   // 256

    if (b < NCSR) {
        for (int e = b * 256 + tid; e < EE; e += NCSR * 256)
            atomicAdd(&g_deg[e_dst[e]], 1);
        gbar(1);

        int pre[4], texcl = 0, prefix = 0;
        __shared__ int s_w[32];
        if (b < 20) {
            const int base = b * 1024 + tid * 4;
            int local = 0;
#pragma unroll
            for (int i = 0; i < 4; i++) {
                int idx = base + i;
                int v = (idx < NN) ? g_deg[idx] : 0;
                pre[i] = local; local += v;
            }
            const int lane = tid & 31, wid = tid >> 5;
            int x = local;
#pragma unroll
            for (int o = 1; o < 32; o <<= 1) {
                int y = __shfl_up_sync(0xffffffffu, x, o);
                if (lane >= o) x += y;
            }
            if (lane == 31) s_w[wid] = x;
            __syncthreads();
            if (wid == 0) {
                int s = (lane < 8) ? s_w[lane] : 0;
#pragma unroll
                for (int o = 1; o < 8; o <<= 1) {
                    int y = __shfl_up_sync(0xffffffffu, s, o);
                    if (lane >= o) s += y;
                }
                if (lane < 8) s_w[lane] = s;
            }
            __syncthreads();
            texcl = (x - local) + (wid > 0 ? s_w[wid - 1] : 0);
            if (tid == 0) { c_bsum[b] = s_w[7]; __threadfence(); }
        }
        gbar(2);
        if (b < 20) {
            for (int j = 0; j < b; j++) prefix += c_bsum[j];
            const int base = b * 1024 + tid * 4;
#pragma unroll
            for (int i = 0; i < 4; i++) {
                int idx = base + i;
                if (idx < NN) g_off[idx] = prefix + texcl + pre[i];
            }
        }
        gbar(3);

        for (int e = b * 256 + tid; e < EE; e += NCSR * 256) {
            int d = e_dst[e];
            int pos = atomicAdd(&g_off[d], 1);
            g_srcs[pos] = e_src[e];
        }
    } else if (b < MB_G1) {
        __shared__ float w[2][4 * HH];
        int sub = tid >> 7, t = tid & 127;
        const float* W = sub ? Wd1 : Ws1;
        for (int i = t; i < 4 * HH; i += 128) w[sub][i] = W[i];
        __syncthreads();
        float* O = sub ? g_hd1 : g_hs1;
        int n0 = (b - NCSR) * 16, n1 = min(NN, n0 + 16);
        for (int n = n0; n < n1; n++) {
            float4 f = *(const float4*)&feat[n * 4];
            O[n * HH + t] = f.x * w[sub][t] + f.y * w[sub][HH + t]
                          + f.z * w[sub][2 * HH + t] + f.w * w[sub][3 * HH + t];
        }
    } else if (b < MB_PE) {
        int idx = (b - MB_G1) * 256 + tid;
        int s = idx / DD, d = idx % DD;
        int i2 = d >> 1;
        float div = __expf((float)(2 * i2) * (-9.210340371976184f / (float)DD));
        float ang = (float)s * div;
        g_pe[idx] = (d & 1) ? cosf(ang) : sinf(ang);
    } else if (b < MB_WS) {
        int i = (b - MB_PE) * 256 + tid;
        int n = i >> 7, k = i & 127;
        float ws = Ws[k * DD + n];
        __nv_bfloat16 h = __float2bfloat16(ws);
        g_wsh[i] = h;
        g_wsl[i] = __float2bfloat16(ws - __bfloat162float(h));
        float wd = Wd[k * DD + n];
        h = __float2bfloat16(wd);
        g_wdh[i] = h;
        g_wdl[i] = __float2bfloat16(wd - __bfloat162float(h));
    } else if (b < MB_TK) {
        int j = (b - MB_WS) * 256 + tid;
        if (j < BS) {
            int v = trj[j];
            t_next[j] = atomicExch(&t_head[v], j);
            if (atomicExch(&g_flag[v], 1) == 0) {
                int p = atomicAdd(&g_misc[0], 1);
                g_list[p] = v;
            }
        }
    } else {
        int r = b - MB_TK;
        if (tid < 192) {
            int mn = mins[r], wk = wkd[r], dy = day[r], gd = grd[r];
            int s = r & (SS - 1);
            int j = tid * 4;
            float4 a = *(const float4*)&g_pe[s * DD + j];
            float4 c = *(const float4*)&wk_tab[wk * DD + j];
            float4 d = *(const float4*)&dayt_tab[mn * DD + j];
            float4 e = *(const float4*)&day_tab[dy * DD + j];
            float4 f = *(const float4*)&grid_tab[gd * DD + j];
            float4 o;
            o.x = a.x + c.x + d.x + e.x + f.x;
            o.y = a.y + c.y + d.y + e.y + f.y;
            o.z = a.z + c.z + d.z + e.z + f.z;
            o.w = a.w + c.w + d.w + e.w + f.w;
            *(float4*)&out[r * DD + j] = o;
        }
    }
}

// ---------------- layer-1: warp per node, online softmax; emit bf16 hi/lo ----------------
__global__ void k_layer1(const float* __restrict__ attn1) {
    int v = (blockIdx.x << 3) + (threadIdx.x >> 5);
    if (v >= NN) return;
    int lane = threadIdx.x & 31;
    int jb = lane * 4;

    float4 hd = *(const float4*)&g_hd1[v * HH + jb];
    float4 at = *(const float4*)&attn1[jb];
    float4 acc = make_float4(0.f, 0.f, 0.f, 0.f);
    float m = -INFINITY, den = 0.f;

    int dg = g_deg[v];
    int st = g_off[v] - dg;           // END - deg
    for (int e = 0; e < dg; e++) {
        int u = g_srcs[st + e];
        float4 hs = *(const float4*)&g_hs1[u * HH + jb];
        float s = lrelu(hs.x + hd.x) * at.x + lrelu(hs.y + hd.y) * at.y
                + lrelu(hs.z + hd.z) * at.z + lrelu(hs.w + hd.w) * at.w;
        s += __shfl_xor_sync(0xffffffffu, s, 1);
        s += __shfl_xor_sync(0xffffffffu, s, 2);
        float nm = fmaxf(m, s);
        float c = __expf(m - nm);
        float p = __expf(s - nm);
        den = den * c + p;
        acc.x = acc.x * c + p * hs.x;
        acc.y = acc.y * c + p * hs.y;
        acc.z = acc.z * c + p * hs.z;
        acc.w = acc.w * c + p * hs.w;
        m = nm;
    }
    float inv = 1.f / den;
    float o[4];
    o[0] = elu1(acc.x * inv); o[1] = elu1(acc.y * inv);
    o[2] = elu1(acc.z * inv); o[3] = elu1(acc.w * inv);
#pragma unroll
    for (int i = 0; i < 4; i++) {
        __nv_bfloat16 h = __float2bfloat16(o[i]);
        g_h1h[v * HH + jb + i] = h;
        g_h1l[v * HH + jb + i] = __float2bfloat16(o[i] - __bfloat162float(h));
    }
}

// ---------------- layer-2 GEMM: N-resident; A resident, B cp.async double-buffered 32-col ----------------
#define NCH (DD / 32)           // 24 chunks
#define SM_A_LO (128 * STRD)
#define SM_B0   (256 * STRD)
#define SM_BUF  (64 * STRD)     // one buffer: Bh 32 rows + Bl 32 rows
__global__ void __launch_bounds__(256, 2) k_gemm2_mma(
        const __nv_bfloat16* __restrict__ Bh0, const __nv_bfloat16* __restrict__ Bl0,
        const __nv_bfloat16* __restrict__ Bh1, const __nv_bfloat16* __restrict__ Bl1,
        float* __restrict__ C0, float* __restrict__ C1) {
    extern __shared__ __nv_bfloat16 sm[];

    const int use_list = blockIdx.y;
    const int M_eff = use_list ? g_misc[0] : NN;
    const int bm = blockIdx.x;
    if (bm * 128 >= M_eff) return;
    const __nv_bfloat16* Bh = use_list ? Bh1 : Bh0;
    const __nv_bfloat16* Bl = use_list ? Bl1 : Bl0;
    float* C = use_list ? C1 : C0;
    const int row0 = bm * 128;
    const int tid = threadIdx.x;
    const uint32_t smb = smem_u32(sm);

    // B prefetch: chunk bn -> buffer buf (1024 x 16B cp.async over 256 threads)
    auto issueB = [&](int bn, int buf) {
        const int n0 = bn * 32;
        const uint32_t bbase = smb + (uint32_t)(SM_B0 + buf * SM_BUF) * 2;
#pragma unroll
        for (int i = tid; i < 1024; i += 256) {
            int plane = i >> 9;                       // 0: hi, 1: lo
            int r = (i >> 4) & 31, ck = i & 15;
            uint32_t sa = bbase + (uint32_t)(plane * 32 * STRD + r * STRD + ck * 8) * 2;
            const __nv_bfloat16* g = (plane ? Bl : Bh) + (n0 + r) * HH + ck * 8;
            CP_ASYNC16(sa, g);
        }
    };

    issueB(0, 0); CP_COMMIT();
    issueB(1, 1); CP_COMMIT();

    // load A tile (hi/lo) once with plain loads (overlaps with cp.async in flight)
    const uint4 z4 = make_uint4(0, 0, 0, 0);
    for (int i = tid; i < 2048; i += 256) {
        int r = i >> 4, ck = i & 15;
        int so = r * STRD + ck * 8;
        int gr = row0 + r;
        uint4 vh = z4, vl = z4;
        if (gr < M_eff) {
            int rr = use_list ? g_list[gr] : gr;
            vh = *(const uint4*)&g_h1h[rr * HH + ck * 8];
            vl = *(const uint4*)&g_h1l[rr * HH + ck * 8];
        }
        *(uint4*)&sm[so] = vh;
        *(uint4*)&sm[SM_A_LO + so] = vl;
    }

    const int wid = tid >> 5, lane = tid & 31;
    const int wm = (wid >> 1) * 32;     // 4 m-groups of 32
    const int wn = (wid & 1) * 16;      // 2 n-groups of 16

    const int a_row = wm + (lane & 15);
    const int a_kof = (lane >> 4) * 8;
    const int q = lane >> 3, rrow = lane & 7;
    const int b_nof = ((q >> 1) ? 8 : 0) + rrow;
    const int b_kof = (q & 1) * 8;

    const int gid = lane >> 2, tig = lane & 3;
    int grow0 = row0 + wm + gid;
    bool v00 = (grow0      ) < M_eff, v01 = (grow0 + 8 ) < M_eff;
    bool v10 = (grow0 + 16 ) < M_eff, v11 = (grow0 + 24) < M_eff;
    int rr00 = v00 ? (use_list ? g_list[grow0      ] : grow0      ) : 0;
    int rr01 = v01 ? (use_list ? g_list[grow0 + 8  ] : grow0 + 8  ) : 0;
    int rr10 = v10 ? (use_list ? g_list[grow0 + 16 ] : grow0 + 16 ) : 0;
    int rr11 = v11 ? (use_list ? g_list[grow0 + 24 ] : grow0 + 24 ) : 0;

    for (int bn = 0; bn < NCH; bn++) {
        if (bn + 2 < NCH) { CP_WAIT1(); } else { CP_WAIT0(); }
        __syncthreads();

        const int buf = bn & 1;
        const uint32_t sBh = smb + (uint32_t)(SM_B0 + buf * SM_BUF) * 2;
        const uint32_t sBl = sBh + (uint32_t)(32 * STRD) * 2;
        const int n0 = bn * 32;

        float acc[2][2][4];
#pragma unroll
        for (int mt = 0; mt < 2; mt++)
#pragma unroll
            for (int nt = 0; nt < 2; nt++)
#pragma unroll
                for (int c = 0; c < 4; c++) acc[mt][nt][c] = 0.f;

#pragma unroll
        for (int ks = 0; ks < 8; ks++) {
            const int kbase = ks * 16;
            uint32_t ah[2][4], al[2][4], bh[2][2], bl[2][2];
#pragma unroll
            for (int mt = 0; mt < 2; mt++) {
                uint32_t ad = smb + (uint32_t)((a_row + mt * 16) * STRD + kbase + a_kof) * 2;
                LDSM_X4(ah[mt][0], ah[mt][1], ah[mt][2], ah[mt][3], ad);
                LDSM_X4(al[mt][0], al[mt][1], al[mt][2], al[mt][3], ad + (uint32_t)SM_A_LO * 2);
            }
            {
                uint32_t bd = sBh + (uint32_t)((wn + b_nof) * STRD + kbase + b_kof) * 2;
                LDSM_X4(bh[0][0], bh[0][1], bh[1][0], bh[1][1], bd);
                uint32_t bd2 = sBl + (uint32_t)((wn + b_nof) * STRD + kbase + b_kof) * 2;
                LDSM_X4(bl[0][0], bl[0][1], bl[1][0], bl[1][1], bd2);
            }
#pragma unroll
            for (int mt = 0; mt < 2; mt++)
#pragma unroll
                for (int nt = 0; nt < 2; nt++) {
                    MMA16816(acc[mt][nt], ah[mt][0], ah[mt][1], ah[mt][2], ah[mt][3],
                             bh[nt][0], bh[nt][1]);
                    MMA16816(acc[mt][nt], al[mt][0], al[mt][1], al[mt][2], al[mt][3],
                             bh[nt][0], bh[nt][1]);
                    MMA16816(acc[mt][nt], ah[mt][0], ah[mt][1], ah[mt][2], ah[mt][3],
                             bl[nt][0], bl[nt][1]);
                }
        }

#pragma unroll
        for (int mt = 0; mt < 2; mt++) {
            bool v0 = mt ? v10 : v00, v1 = mt ? v11 : v01;
            int r0 = mt ? rr10 : rr00, r1 = mt ? rr11 : rr01;
#pragma unroll
            for (int nt = 0; nt < 2; nt++) {
                int col = n0 + wn + nt * 8 + tig * 2;
                if (v0) *(float2*)&C[(size_t)r0 * DD + col] = make_float2(acc[mt][nt][0], acc[mt][nt][1]);
                if (v1) *(float2*)&C[(size_t)r1 * DD + col] = make_float2(acc[mt][nt][2], acc[mt][nt][3]);
            }
        }
        __syncthreads();       // all warps done reading buf before refill
        if (bn + 2 < NCH) { issueB(bn + 2, buf); CP_COMMIT(); }
    }
}

// ---------------- layer-2: TWO warps per node (384 dims each); adds into out via token list ----------------
__global__ void __launch_bounds__(256) k_layer2(const float* __restrict__ attn2,
                                                float* __restrict__ out) {
    __shared__ float at_sh[DD];
    __shared__ float s_part[4][4];      // [pair][w2 + 2*(e&1)] double-buffered partial scores
    for (int i = threadIdx.x; i < 256; i += 256) {}   // keep layout
    for (int i = threadIdx.x; i < DD; i += 256) at_sh[i] = attn2[i];
    __syncthreads();

    const int pair = threadIdx.x >> 6;            // 0..3 (node slot in block)
    const int li = blockIdx.x * 4 + pair;
    if (li >= g_misc[0]) return;
    const int v = g_list[li];
    const int t64 = threadIdx.x & 63;
    const int w2 = t64 >> 5;
    const int lane = t64 & 31;
    const int dbase = w2 * 384 + lane * 4;
    const int barid = 8 + pair;

    float4 hd[3], acc[3], at[3];
#pragma unroll
    for (int i = 0; i < 3; i++) {
        hd[i] = *(const float4*)&g_hd2[v * DD + dbase + i * 128];
        at[i] = *(const float4*)&at_sh[dbase + i * 128];
        acc[i] = make_float4(0.f, 0.f, 0.f, 0.f);
    }
    float m = -INFINITY, den = 0.f;

    const int dg = g_deg[v];
    const int st = g_off[v] - dg;
    for (int e = 0; e < dg; e++) {
        int u = g_srcs[st + e];
        const float* hrow = &g_hs2[u * DD];
        float4 hs[3];
        float s = 0.f;
#pragma unroll
        for (int i = 0; i < 3; i++) {
            hs[i] = *(const float4*)&hrow[dbase + i * 128];
            s += lrelu(hs[i].x + hd[i].x) * at[i].x + lrelu(hs[i].y + hd[i].y) * at[i].y
               + lrelu(hs[i].z + hd[i].z) * at[i].z + lrelu(hs[i].w + hd[i].w) * at[i].w;
        }
#pragma unroll
        for (int o = 16; o; o >>= 1) s += __shfl_xor_sync(0xffffffffu, s, o);
        int buf = (e & 1) * 2;
        if (lane == 0) s_part[pair][w2 + buf] = s;
        asm volatile("bar.sync %0, %1;" :: "r"(barid), "r"(64) : "memory");
        float stot = s_part[pair][buf] + s_part[pair][buf + 1];

        float nm = fmaxf(m, stot);
        float c = __expf(m - nm);
        float p = __expf(stot - nm);
        den = den * c + p;
#pragma unroll
        for (int i = 0; i < 3; i++) {
            acc[i].x = acc[i].x * c + p * hs[i].x;
            acc[i].y = acc[i].y * c + p * hs[i].y;
            acc[i].z = acc[i].z * c + p * hs[i].z;
            acc[i].w = acc[i].w * c + p * hs[i].w;
        }
        m = nm;
    }
    float inv = 1.f / den;
    float4 h2[3];
#pragma unroll
    for (int i = 0; i < 3; i++)
        h2[i] = make_float4(acc[i].x * inv, acc[i].y * inv, acc[i].z * inv, acc[i].w * inv);

    for (int r = t_head[v]; r != -1; r = t_next[r]) {
        float* op = &out[(size_t)r * DD + dbase];
#pragma unroll
        for (int i = 0; i < 3; i++) {
            float4 o = *(float4*)&op[i * 128];
            o.x += h2[i].x; o.y += h2[i].y; o.z += h2[i].z; o.w += h2[i].w;
            *(float4*)&op[i * 128] = o;
        }
    }
}

// ---------------- launch ----------------
extern "C" void kernel_launch(void* const* d_in, const int* in_sizes, int n_in,
                              void* d_out, int out_size) {
    const int*   trj      = (const int*)d_in[0];
    const int*   min_list = (const int*)d_in[1];
    const int*   wkd_list = (const int*)d_in[2];
    const int*   day_list = (const int*)d_in[3];
    const int*   grd_list = (const int*)d_in[4];
    const int*   e_src    = (const int*)d_in[6];
    const int*   e_dst    = (const int*)d_in[7];
    const float* feat     = (const float*)d_in[8];
    const float* W_src1   = (const float*)d_in[9];
    const float* W_dst1   = (const float*)d_in[10];
    const float* attn1    = (const float*)d_in[11];
    const float* W_src2   = (const float*)d_in[12];
    const float* W_dst2   = (const float*)d_in[13];
    const float* attn2    = (const float*)d_in[14];
    const float* grid_tab = (const float*)d_in[15];
    const float* dayt_tab = (const float*)d_in[16];
    const float* wk_tab   = (const float*)d_in[17];
    const float* day_tab  = (const float*)d_in[18];
    float* out = (float*)d_out;

    const int smem_bytes = (256 + 128) * STRD * 2;   // 104448
    static bool once = false;
    static void *p_deg, *p_flag, *p_thead;
    if (!once) {
        cudaFuncSetAttribute(k_gemm2_mma, cudaFuncAttributeMaxDynamicSharedMemorySize, smem_bytes);
        cudaGetSymbolAddress(&p_deg, g_deg);
        cudaGetSymbolAddress(&p_flag, g_flag);
        cudaGetSymbolAddress(&p_thead, t_head);
        once = true;
    }

    __nv_bfloat16 *wsh, *wsl, *wdh, *wdl;
    cudaGetSymbolAddress((void**)&wsh, g_wsh);
    cudaGetSymbolAddress((void**)&wsl, g_wsl);
    cudaGetSymbolAddress((void**)&wdh, g_wdh);
    cudaGetSymbolAddress((void**)&wdl, g_wdl);
    float *hs2, *hd2;
    cudaGetSymbolAddress((void**)&hs2, g_hs2);
    cudaGetSymbolAddress((void**)&hd2, g_hd2);

    cudaMemsetAsync(p_deg, 0, NN * sizeof(int), 0);
    cudaMemsetAsync(p_flag, 0, NN * sizeof(int), 0);
    cudaMemsetAsync(p_thead, 0xFF, NN * sizeof(int), 0);    // -1

    k_zero<<<1, 32>>>();                                                  // 1
    k_mega<<<MB_TAB, 256>>>(e_src, e_dst, feat, W_src1, W_dst1, W_src2, W_dst2,
                            trj, min_list, wkd_list, day_list, grd_list,
                            grid_tab, dayt_tab, wk_tab, day_tab, out);    // 2
    k_layer1<<<(NN + 7) / 8, 256>>>(attn1);                               // 3
    dim3 g2((NN + 127) / 128, 2);
    k_gemm2_mma<<<g2, 256, smem_bytes>>>(wsh, wsl, wdh, wdl, hs2, hd2);   // 4 <- profiled
    k_layer2<<<(NN + 3) / 4, 256>>>(attn2, out);                          // 5
}